// round 1
// baseline (speedup 1.0000x reference)
#include <cuda_runtime.h>
#include <cuda_bf16.h>
#include <cstdint>

#define N_NODES  100000
#define HIDDEN   256
#define N_MOVES  500000
#define N_GRAPHS 512

// ---------------- scratch (static __device__ — no allocations) ----------------
__device__ float    g_PQ[(size_t)N_NODES * 512];   // [n][0:256]=P, [n][256:512]=Q
__device__ float    g_logits[N_MOVES];
__device__ int      g_mb[N_MOVES];                 // move_batch
__device__ unsigned g_gmax[N_GRAPHS];              // order-encoded float max
__device__ float    g_gsum[N_GRAPHS];
__device__ int      g_is64;                        // index dtype flag

// order-preserving float<->uint encoding for atomicMax
__device__ __forceinline__ unsigned enc_f(float f) {
    unsigned u = __float_as_uint(f);
    return (u & 0x80000000u) ? ~u : (u | 0x80000000u);
}
__device__ __forceinline__ float dec_f(unsigned u) {
    u = (u & 0x80000000u) ? (u & 0x7fffffffu) : ~u;
    return __uint_as_float(u);
}

// ---------------- dtype detection: int64 vs int32 index arrays ----------------
__global__ void detect_kernel(const unsigned* __restrict__ lm) {
    if (threadIdx.x == 0 && blockIdx.x == 0) {
        int all0 = 1;
        #pragma unroll 1
        for (int i = 1; i < 128; i += 2) all0 &= (lm[i] == 0u);
        g_is64 = all0;   // odd words all zero => little-endian int64 payload
    }
}

__global__ void init_kernel() {
    int i = blockIdx.x * blockDim.x + threadIdx.x;
    if (i < N_GRAPHS) { g_gmax[i] = 0u; g_gsum[i] = 0.0f; }
}

// ---------------- GEMM: PQ[n, j] ----------------
// j < 256:  sum_k emb[n,k] * W1[k, j]
// j >= 256: sum_k emb[n,k] * W1[256+k, j-256]
#define BM 128
#define BN 128
#define BK 16

__global__ __launch_bounds__(256) void gemm_kernel(const float* __restrict__ emb,
                                                   const float* __restrict__ W1) {
    __shared__ float As[BK][BM + 4];
    __shared__ float Bs[BK][BN];

    const int m0 = blockIdx.x * BM;
    const int n0 = blockIdx.y * BN;
    const float* Bptr = W1 + (n0 >= 256 ? 256 * 256 : 0);
    const int jbase = n0 & 255;

    const int tid = threadIdx.x;
    const int tx = tid & 15;        // 0..15 -> 8 cols each
    const int ty = tid >> 4;        // 0..15 -> 8 rows each

    float acc[8][8];
    #pragma unroll
    for (int i = 0; i < 8; i++)
        #pragma unroll
        for (int j = 0; j < 8; j++) acc[i][j] = 0.0f;

    for (int k0 = 0; k0 < HIDDEN; k0 += BK) {
        // load A tile: 128 rows x 16 k, float4 along k
        #pragma unroll
        for (int l = 0; l < 2; l++) {
            int idx = tid + l * 256;         // 0..511 float4 slots
            int r   = idx >> 2;              // row 0..127
            int c4  = (idx & 3) * 4;         // k offset 0,4,8,12
            int gm  = m0 + r;
            float4 v = make_float4(0.f, 0.f, 0.f, 0.f);
            if (gm < N_NODES)
                v = *reinterpret_cast<const float4*>(emb + (size_t)gm * HIDDEN + k0 + c4);
            As[c4 + 0][r] = v.x; As[c4 + 1][r] = v.y;
            As[c4 + 2][r] = v.z; As[c4 + 3][r] = v.w;
        }
        // load B tile: 16 k x 128 cols, float4 along cols
        #pragma unroll
        for (int l = 0; l < 2; l++) {
            int idx = tid + l * 256;         // 0..511
            int r   = idx >> 5;              // k 0..15
            int c4  = (idx & 31) * 4;        // col 0..124
            float4 v = *reinterpret_cast<const float4*>(
                Bptr + (size_t)(k0 + r) * 256 + jbase + c4);
            *reinterpret_cast<float4*>(&Bs[r][c4]) = v;
        }
        __syncthreads();

        #pragma unroll
        for (int k = 0; k < BK; k++) {
            float a[8], b[8];
            *reinterpret_cast<float4*>(&a[0]) = *reinterpret_cast<const float4*>(&As[k][ty * 8 + 0]);
            *reinterpret_cast<float4*>(&a[4]) = *reinterpret_cast<const float4*>(&As[k][ty * 8 + 4]);
            *reinterpret_cast<float4*>(&b[0]) = *reinterpret_cast<const float4*>(&Bs[k][tx * 8 + 0]);
            *reinterpret_cast<float4*>(&b[4]) = *reinterpret_cast<const float4*>(&Bs[k][tx * 8 + 4]);
            #pragma unroll
            for (int i = 0; i < 8; i++)
                #pragma unroll
                for (int j = 0; j < 8; j++)
                    acc[i][j] = fmaf(a[i], b[j], acc[i][j]);
        }
        __syncthreads();
    }

    #pragma unroll
    for (int i = 0; i < 8; i++) {
        int gm = m0 + ty * 8 + i;
        if (gm < N_NODES) {
            float* dst = g_PQ + (size_t)gm * 512 + n0 + tx * 8;
            *reinterpret_cast<float4*>(dst)     = make_float4(acc[i][0], acc[i][1], acc[i][2], acc[i][3]);
            *reinterpret_cast<float4*>(dst + 4) = make_float4(acc[i][4], acc[i][5], acc[i][6], acc[i][7]);
        }
    }
}

// ---------------- per-edge logits + segment max ----------------
__global__ __launch_bounds__(256) void edge_kernel(const unsigned* __restrict__ lm,
                                                   const unsigned* __restrict__ batchw,
                                                   const float* __restrict__ b1,
                                                   const float* __restrict__ W2,
                                                   const float* __restrict__ b2) {
    __shared__ float sb1[HIDDEN];
    __shared__ float sW2[HIDDEN];
    __shared__ float sb2;
    const int tid = threadIdx.x;
    if (tid < HIDDEN) { sb1[tid] = b1[tid]; sW2[tid] = W2[tid]; }
    if (tid == 0) sb2 = b2[0];
    __syncthreads();

    const int warp = tid >> 5;
    const int lane = tid & 31;
    const int e = blockIdx.x * 8 + warp;
    if (e >= N_MOVES) return;

    const int is64 = g_is64;
    unsigned s, t;
    if (is64) {
        s = lm[2 * (size_t)e];
        t = lm[2 * ((size_t)N_MOVES + e)];
    } else {
        s = lm[e];
        t = lm[(size_t)N_MOVES + e];
    }

    const float4* P = reinterpret_cast<const float4*>(g_PQ + (size_t)s * 512);
    const float4* Q = reinterpret_cast<const float4*>(g_PQ + (size_t)t * 512 + 256);

    float acc = 0.0f;
    #pragma unroll
    for (int it = 0; it < 2; it++) {
        int j4 = lane + it * 32;      // float4 index 0..63
        float4 p = P[j4];
        float4 q = Q[j4];
        int j = j4 * 4;
        float h;
        h = p.x + q.x + sb1[j + 0]; h = fmaxf(h, 0.f); acc = fmaf(h, sW2[j + 0], acc);
        h = p.y + q.y + sb1[j + 1]; h = fmaxf(h, 0.f); acc = fmaf(h, sW2[j + 1], acc);
        h = p.z + q.z + sb1[j + 2]; h = fmaxf(h, 0.f); acc = fmaf(h, sW2[j + 2], acc);
        h = p.w + q.w + sb1[j + 3]; h = fmaxf(h, 0.f); acc = fmaf(h, sW2[j + 3], acc);
    }
    #pragma unroll
    for (int o = 16; o > 0; o >>= 1)
        acc += __shfl_down_sync(0xffffffffu, acc, o);

    if (lane == 0) {
        float logit = acc + sb2;
        unsigned g = is64 ? batchw[2 * (size_t)s] : batchw[s];
        g_logits[e] = logit;
        g_mb[e] = (int)g;
        atomicMax(&g_gmax[g], enc_f(logit));
    }
}

// ---------------- exp + segment sum ----------------
__global__ void expsum_kernel(float* __restrict__ out) {
    int e = blockIdx.x * blockDim.x + threadIdx.x;
    if (e >= N_MOVES) return;
    int g = g_mb[e];
    float m = dec_f(g_gmax[g]);
    float ex = expf(g_logits[e] - m);
    out[e] = ex;
    atomicAdd(&g_gsum[g], ex);
}

// ---------------- normalize ----------------
__global__ void norm_kernel(float* __restrict__ out) {
    int e = blockIdx.x * blockDim.x + threadIdx.x;
    if (e >= N_MOVES) return;
    out[e] = out[e] / (g_gsum[g_mb[e]] + 1e-16f);
}

// ---------------- launch ----------------
extern "C" void kernel_launch(void* const* d_in, const int* in_sizes, int n_in,
                              void* d_out, int out_size) {
    const float*    emb    = (const float*)d_in[0];
    const unsigned* lm     = (const unsigned*)d_in[1];
    const unsigned* batchw = (const unsigned*)d_in[2];
    const float*    W1     = (const float*)d_in[3];
    const float*    b1     = (const float*)d_in[4];
    const float*    W2     = (const float*)d_in[5];
    const float*    b2     = (const float*)d_in[6];
    float*          out    = (float*)d_out;
    (void)in_sizes; (void)n_in; (void)out_size;

    detect_kernel<<<1, 32>>>(lm);
    init_kernel<<<1, N_GRAPHS>>>();

    dim3 ggrid((N_NODES + BM - 1) / BM, 512 / BN);
    gemm_kernel<<<ggrid, 256>>>(emb, W1);

    edge_kernel<<<N_MOVES / 8, 256>>>(lm, batchw, b1, W2, b2);

    int eb = (N_MOVES + 255) / 256;
    expsum_kernel<<<eb, 256>>>(out);
    norm_kernel<<<eb, 256>>>(out);
}

// round 5
// speedup vs baseline: 1.2191x; 1.2191x over previous
#include <cuda_runtime.h>
#include <cuda_bf16.h>
#include <mma.h>
#include <cstdint>

using namespace nvcuda;

#define N_NODES  100000
#define HIDDEN   256
#define N_MOVES  500000
#define N_GRAPHS 512
#define M_TILES  1564              /* M_PAD / 64 */
#define M_PAD    100096            /* 1564 * 64, >= N_NODES, divisible by 64 */

// ---------------- scratch (static __device__ — no allocations) ----------------
__device__ __nv_bfloat16 g_Ah[(size_t)M_PAD * 256];
__device__ __nv_bfloat16 g_Al[(size_t)M_PAD * 256];
__device__ __nv_bfloat16 g_Wh[256 * 512];
__device__ __nv_bfloat16 g_Wl[256 * 512];
__device__ float    g_PQ[(size_t)M_PAD * 512];   // [n][0:256]=P, [n][256:512]=Q
__device__ float    g_logits[N_MOVES];
__device__ int      g_mb[N_MOVES];
__device__ unsigned g_gmax[N_GRAPHS];
__device__ float    g_gsum[N_GRAPHS];
__device__ int      g_is64;

__device__ __forceinline__ unsigned enc_f(float f) {
    unsigned u = __float_as_uint(f);
    return (u & 0x80000000u) ? ~u : (u | 0x80000000u);
}
__device__ __forceinline__ float dec_f(unsigned u) {
    u = (u & 0x80000000u) ? (u & 0x7fffffffu) : ~u;
    return __uint_as_float(u);
}

// ---------------- dtype detection: int64 vs int32 index arrays ----------------
__global__ void detect_kernel(const unsigned* __restrict__ lm) {
    if (threadIdx.x == 0 && blockIdx.x == 0) {
        int all0 = 1;
        #pragma unroll 1
        for (int i = 1; i < 128; i += 2) all0 &= (lm[i] == 0u);
        g_is64 = all0;
    }
}

__global__ void init_kernel() {
    int i = blockIdx.x * blockDim.x + threadIdx.x;
    if (i < N_GRAPHS) { g_gmax[i] = 0u; g_gsum[i] = 0.0f; }
}

// ---------------- A conversion: fp32 -> bf16 hi/lo (linear layout) ----------------
__global__ __launch_bounds__(256) void aconv_kernel(const float* __restrict__ emb) {
    int idx = blockIdx.x * blockDim.x + threadIdx.x;   // one thread = 8 k of one row
    if (idx >= M_PAD * 32) return;
    int r  = idx >> 5;
    int k0 = (idx & 31) * 8;
    float v[8];
    if (r < N_NODES) {
        const float4* p = reinterpret_cast<const float4*>(emb + (size_t)r * HIDDEN + k0);
        float4 x = p[0], y = p[1];
        v[0] = x.x; v[1] = x.y; v[2] = x.z; v[3] = x.w;
        v[4] = y.x; v[5] = y.y; v[6] = y.z; v[7] = y.w;
    } else {
        #pragma unroll
        for (int i = 0; i < 8; i++) v[i] = 0.0f;
    }
    __align__(16) __nv_bfloat16 h[8];
    __align__(16) __nv_bfloat16 l[8];
    #pragma unroll
    for (int i = 0; i < 8; i++) {
        h[i] = __float2bfloat16(v[i]);
        l[i] = __float2bfloat16(v[i] - __bfloat162float(h[i]));
    }
    size_t off = (size_t)r * 256 + k0;
    *reinterpret_cast<uint4*>(g_Ah + off) = *reinterpret_cast<uint4*>(h);
    *reinterpret_cast<uint4*>(g_Al + off) = *reinterpret_cast<uint4*>(l);
}

// ---------------- W prep: W1 (512,256) -> combined [256 k][512 n] bf16 hi/lo ------
// n < 256: W[k][n] = W1[k][n];  n >= 256: W[k][n] = W1[256+k][n-256]
__global__ __launch_bounds__(256) void wprep_kernel(const float* __restrict__ W1) {
    int idx = blockIdx.x * blockDim.x + threadIdx.x;   // 0..131071
    if (idx >= 2 * 256 * 256) return;
    int n = idx & 255;
    int k = (idx >> 8) & 255;
    int T = idx >> 16;
    float v = W1[((size_t)(T * 256 + k)) * 256 + n];
    __nv_bfloat16 h = __float2bfloat16(v);
    __nv_bfloat16 l = __float2bfloat16(v - __bfloat162float(h));
    size_t off = (size_t)k * 512 + T * 256 + n;
    g_Wh[off] = h;
    g_Wl[off] = l;
}

// ---------------- WMMA bf16-split GEMM: PQ[M_PAD,512] = A[M_PAD,256] @ W[256,512] --
// CTA tile 64(M) x 128(N), K chunk 64. 8 warps, warp tile 32x32.
// 3-term split: Ah*Wh + Ah*Wl + Al*Wh  (Al*Wl term ~2^-18, dropped)
#define BM 64
#define BN 128
#define BK 64
#define LDA 72     /* 64 + 8 pad; *2B = 144 (16B multiple) */
#define LDW 136    /* 128 + 8 pad; *2B = 272 (16B multiple) */
#define SM_A (BM * LDA)                 /* 4608 elems */
#define SM_W (BK * LDW)                 /* 8704 elems */
#define GEMM_SMEM ((2 * SM_A + 2 * SM_W) * 2)   /* 53248 bytes */

__global__ __launch_bounds__(256) void gemm_wmma_kernel() {
    extern __shared__ __align__(16) __nv_bfloat16 sm[];
    __nv_bfloat16* sAh = sm;
    __nv_bfloat16* sAl = sAh + SM_A;
    __nv_bfloat16* sWh = sAl + SM_A;
    __nv_bfloat16* sWl = sWh + SM_W;

    const int tid = threadIdx.x;
    const int wid = tid >> 5;
    const int warp_m = wid & 1;        // 0..1  -> 32-row slice
    const int warp_n = wid >> 1;       // 0..3  -> 32-col slice
    const int n0 = blockIdx.x * BN;    // n fastest: 4 CTAs share one A tile (L2)
    const int m0 = blockIdx.y * BM;

    wmma::fragment<wmma::accumulator, 16, 16, 16, float> c[2][2];
    #pragma unroll
    for (int i = 0; i < 2; i++)
        #pragma unroll
        for (int j = 0; j < 2; j++) wmma::fill_fragment(c[i][j], 0.0f);

    #pragma unroll 1
    for (int kc = 0; kc < 256; kc += BK) {
        // load A hi/lo: 64 rows x 64 k = 512 uint4 each
        #pragma unroll
        for (int it = 0; it < 2; it++) {
            int i = tid + it * 256;
            int row = i >> 3, c8 = (i & 7) * 8;
            size_t src = (size_t)(m0 + row) * 256 + kc + c8;
            size_t dst = (size_t)row * LDA + c8;
            *reinterpret_cast<uint4*>(sAh + dst) = *reinterpret_cast<const uint4*>(g_Ah + src);
            *reinterpret_cast<uint4*>(sAl + dst) = *reinterpret_cast<const uint4*>(g_Al + src);
        }
        // load W hi/lo: 64 k x 128 n = 1024 uint4 each
        #pragma unroll
        for (int it = 0; it < 4; it++) {
            int i = tid + it * 256;
            int row = i >> 4, c8 = (i & 15) * 8;
            size_t src = (size_t)(kc + row) * 512 + n0 + c8;
            size_t dst = (size_t)row * LDW + c8;
            *reinterpret_cast<uint4*>(sWh + dst) = *reinterpret_cast<const uint4*>(g_Wh + src);
            *reinterpret_cast<uint4*>(sWl + dst) = *reinterpret_cast<const uint4*>(g_Wl + src);
        }
        __syncthreads();

        #pragma unroll
        for (int ks = 0; ks < BK; ks += 16) {
            wmma::fragment<wmma::matrix_a, 16, 16, 16, __nv_bfloat16, wmma::row_major> ah[2], al[2];
            wmma::fragment<wmma::matrix_b, 16, 16, 16, __nv_bfloat16, wmma::row_major> bh[2], bl[2];
            #pragma unroll
            for (int i = 0; i < 2; i++) {
                const __nv_bfloat16* ap = sAh + (size_t)(warp_m * 32 + i * 16) * LDA + ks;
                const __nv_bfloat16* lp = sAl + (size_t)(warp_m * 32 + i * 16) * LDA + ks;
                wmma::load_matrix_sync(ah[i], ap, LDA);
                wmma::load_matrix_sync(al[i], lp, LDA);
            }
            #pragma unroll
            for (int j = 0; j < 2; j++) {
                const __nv_bfloat16* bp = sWh + (size_t)ks * LDW + warp_n * 32 + j * 16;
                const __nv_bfloat16* lp = sWl + (size_t)ks * LDW + warp_n * 32 + j * 16;
                wmma::load_matrix_sync(bh[j], bp, LDW);
                wmma::load_matrix_sync(bl[j], lp, LDW);
            }
            #pragma unroll
            for (int i = 0; i < 2; i++)
                #pragma unroll
                for (int j = 0; j < 2; j++) {
                    wmma::mma_sync(c[i][j], ah[i], bh[j], c[i][j]);
                    wmma::mma_sync(c[i][j], ah[i], bl[j], c[i][j]);
                    wmma::mma_sync(c[i][j], al[i], bh[j], c[i][j]);
                }
        }
        __syncthreads();
    }

    #pragma unroll
    for (int i = 0; i < 2; i++)
        #pragma unroll
        for (int j = 0; j < 2; j++) {
            float* dst = g_PQ + (size_t)(m0 + warp_m * 32 + i * 16) * 512
                              + n0 + warp_n * 32 + j * 16;
            wmma::store_matrix_sync(dst, c[i][j], 512, wmma::mem_row_major);
        }
}

// ---------------- per-edge logits + segment max ----------------
__global__ __launch_bounds__(256) void edge_kernel(const unsigned* __restrict__ lm,
                                                   const unsigned* __restrict__ batchw,
                                                   const float* __restrict__ b1,
                                                   const float* __restrict__ W2,
                                                   const float* __restrict__ b2) {
    __shared__ float sb1[HIDDEN];
    __shared__ float sW2[HIDDEN];
    __shared__ float sb2;
    const int tid = threadIdx.x;
    if (tid < HIDDEN) { sb1[tid] = b1[tid]; sW2[tid] = W2[tid]; }
    if (tid == 0) sb2 = b2[0];
    __syncthreads();

    const int warp = tid >> 5;
    const int lane = tid & 31;
    const int e = blockIdx.x * 8 + warp;
    if (e >= N_MOVES) return;

    const int is64 = g_is64;
    unsigned s, t;
    if (is64) {
        s = lm[2 * (size_t)e];
        t = lm[2 * ((size_t)N_MOVES + e)];
    } else {
        s = lm[e];
        t = lm[(size_t)N_MOVES + e];
    }

    const float4* P = reinterpret_cast<const float4*>(g_PQ + (size_t)s * 512);
    const float4* Q = reinterpret_cast<const float4*>(g_PQ + (size_t)t * 512 + 256);

    float acc = 0.0f;
    #pragma unroll
    for (int it = 0; it < 2; it++) {
        int j4 = lane + it * 32;
        float4 p = P[j4];
        float4 q = Q[j4];
        int j = j4 * 4;
        float h;
        h = p.x + q.x + sb1[j + 0]; h = fmaxf(h, 0.f); acc = fmaf(h, sW2[j + 0], acc);
        h = p.y + q.y + sb1[j + 1]; h = fmaxf(h, 0.f); acc = fmaf(h, sW2[j + 1], acc);
        h = p.z + q.z + sb1[j + 2]; h = fmaxf(h, 0.f); acc = fmaf(h, sW2[j + 2], acc);
        h = p.w + q.w + sb1[j + 3]; h = fmaxf(h, 0.f); acc = fmaf(h, sW2[j + 3], acc);
    }
    #pragma unroll
    for (int o = 16; o > 0; o >>= 1)
        acc += __shfl_down_sync(0xffffffffu, acc, o);

    if (lane == 0) {
        float logit = acc + sb2;
        unsigned g = is64 ? batchw[2 * (size_t)s] : batchw[s];
        g_logits[e] = logit;
        g_mb[e] = (int)g;
        atomicMax(&g_gmax[g], enc_f(logit));
    }
}

// ---------------- exp + segment sum ----------------
__global__ void expsum_kernel(float* __restrict__ out) {
    int e = blockIdx.x * blockDim.x + threadIdx.x;
    if (e >= N_MOVES) return;
    int g = g_mb[e];
    float m = dec_f(g_gmax[g]);
    float ex = expf(g_logits[e] - m);
    out[e] = ex;
    atomicAdd(&g_gsum[g], ex);
}

// ---------------- normalize ----------------
__global__ void norm_kernel(float* __restrict__ out) {
    int e = blockIdx.x * blockDim.x + threadIdx.x;
    if (e >= N_MOVES) return;
    out[e] = out[e] / (g_gsum[g_mb[e]] + 1e-16f);
}

// ---------------- launch ----------------
extern "C" void kernel_launch(void* const* d_in, const int* in_sizes, int n_in,
                              void* d_out, int out_size) {
    const float*    emb    = (const float*)d_in[0];
    const unsigned* lm     = (const unsigned*)d_in[1];
    const unsigned* batchw = (const unsigned*)d_in[2];
    const float*    W1     = (const float*)d_in[3];
    const float*    b1     = (const float*)d_in[4];
    const float*    W2     = (const float*)d_in[5];
    const float*    b2     = (const float*)d_in[6];
    float*          out    = (float*)d_out;
    (void)in_sizes; (void)n_in; (void)out_size;

    cudaFuncSetAttribute(gemm_wmma_kernel, cudaFuncAttributeMaxDynamicSharedMemorySize, GEMM_SMEM);

    detect_kernel<<<1, 32>>>(lm);
    init_kernel<<<1, N_GRAPHS>>>();

    aconv_kernel<<<(M_PAD * 32 + 255) / 256, 256>>>(emb);
    wprep_kernel<<<(2 * 256 * 256 + 255) / 256, 256>>>(W1);

    dim3 ggrid(512 / BN, M_TILES);   // x = n tile (fast), y = m tile
    gemm_wmma_kernel<<<ggrid, 256, GEMM_SMEM>>>();

    edge_kernel<<<N_MOVES / 8, 256>>>(lm, batchw, b1, W2, b2);

    int eb = (N_MOVES + 255) / 256;
    expsum_kernel<<<eb, 256>>>(out);
    norm_kernel<<<eb, 256>>>(out);
}

// round 6
// speedup vs baseline: 1.3866x; 1.1374x over previous
#include <cuda_runtime.h>
#include <cuda_bf16.h>
#include <mma.h>
#include <cstdint>

using namespace nvcuda;

#define N_NODES  100000
#define HIDDEN   256
#define N_MOVES  500000
#define N_GRAPHS 512
#define M_PAD    100096            /* divisible by 128 (782 * 128) */

// ---------------- scratch (static __device__ — no allocations) ----------------
__device__ __nv_bfloat16 g_Ah[(size_t)M_PAD * 256];
__device__ __nv_bfloat16 g_Al[(size_t)M_PAD * 256];
__device__ __nv_bfloat16 g_Wh[256 * 512];
__device__ __nv_bfloat16 g_Wl[256 * 512];
__device__ float    g_PQ[(size_t)M_PAD * 512];   // [n][0:256]=P, [n][256:512]=Q
__device__ float    g_logits[N_MOVES];
__device__ int      g_mb[N_MOVES];
__device__ unsigned g_gmax[N_GRAPHS];
__device__ float    g_gsum[N_GRAPHS];
__device__ int      g_is64;

__device__ __forceinline__ unsigned enc_f(float f) {
    unsigned u = __float_as_uint(f);
    return (u & 0x80000000u) ? ~u : (u | 0x80000000u);
}
__device__ __forceinline__ float dec_f(unsigned u) {
    u = (u & 0x80000000u) ? (u & 0x7fffffffu) : ~u;
    return __uint_as_float(u);
}

// ---------------- cp.async helpers ----------------
#define CP_ASYNC16(dst_u32, src_ptr) \
    asm volatile("cp.async.cg.shared.global [%0], [%1], 16;" :: "r"(dst_u32), "l"(src_ptr))
#define CP_COMMIT() asm volatile("cp.async.commit_group;")
#define CP_WAIT(n)  asm volatile("cp.async.wait_group %0;" :: "n"(n))

// ---------------- dtype detection: int64 vs int32 index arrays ----------------
__global__ void detect_kernel(const unsigned* __restrict__ lm) {
    if (threadIdx.x == 0 && blockIdx.x == 0) {
        int all0 = 1;
        #pragma unroll 1
        for (int i = 1; i < 128; i += 2) all0 &= (lm[i] == 0u);
        g_is64 = all0;
    }
}

__global__ void init_kernel() {
    int i = blockIdx.x * blockDim.x + threadIdx.x;
    if (i < N_GRAPHS) { g_gmax[i] = 0u; g_gsum[i] = 0.0f; }
}

// ---------------- A conversion: fp32 -> bf16 hi/lo (linear layout) ----------------
__global__ __launch_bounds__(256) void aconv_kernel(const float* __restrict__ emb) {
    int idx = blockIdx.x * blockDim.x + threadIdx.x;   // one thread = 8 k of one row
    if (idx >= M_PAD * 32) return;
    int r  = idx >> 5;
    int k0 = (idx & 31) * 8;
    float v[8];
    if (r < N_NODES) {
        const float4* p = reinterpret_cast<const float4*>(emb + (size_t)r * HIDDEN + k0);
        float4 x = p[0], y = p[1];
        v[0] = x.x; v[1] = x.y; v[2] = x.z; v[3] = x.w;
        v[4] = y.x; v[5] = y.y; v[6] = y.z; v[7] = y.w;
    } else {
        #pragma unroll
        for (int i = 0; i < 8; i++) v[i] = 0.0f;
    }
    __align__(16) __nv_bfloat16 h[8];
    __align__(16) __nv_bfloat16 l[8];
    #pragma unroll
    for (int i = 0; i < 8; i++) {
        h[i] = __float2bfloat16(v[i]);
        l[i] = __float2bfloat16(v[i] - __bfloat162float(h[i]));
    }
    size_t off = (size_t)r * 256 + k0;
    *reinterpret_cast<uint4*>(g_Ah + off) = *reinterpret_cast<uint4*>(h);
    *reinterpret_cast<uint4*>(g_Al + off) = *reinterpret_cast<uint4*>(l);
}

// ---------------- W prep: W1 (512,256) -> combined [256 k][512 n] bf16 hi/lo ------
__global__ __launch_bounds__(256) void wprep_kernel(const float* __restrict__ W1) {
    int idx = blockIdx.x * blockDim.x + threadIdx.x;   // 0..131071
    if (idx >= 2 * 256 * 256) return;
    int n = idx & 255;
    int k = (idx >> 8) & 255;
    int T = idx >> 16;
    float v = W1[((size_t)(T * 256 + k)) * 256 + n];
    __nv_bfloat16 h = __float2bfloat16(v);
    __nv_bfloat16 l = __float2bfloat16(v - __bfloat162float(h));
    size_t off = (size_t)k * 512 + T * 256 + n;
    g_Wh[off] = h;
    g_Wl[off] = l;
}

// ---------------- WMMA bf16-split GEMM, cp.async double-buffered ----------------
// CTA tile 128x128, 8 warps (4m x 2n), warp tile 32x64, BK=32, 2 stages.
// 3-term split: Ah*Wh + Ah*Wl + Al*Wh
#define BM 128
#define BN 128
#define BK 32
#define LDA 40     /* 32 + 8 pad; row = 80B (16B mult) */
#define LDW 136    /* 128 + 8 pad; row = 272B (16B mult) */
#define STG_AH 0
#define STG_AL (BM * LDA * 2)                   /* 10240 B */
#define STG_WH (2 * BM * LDA * 2)               /* 20480 B */
#define STG_WL (2 * BM * LDA * 2 + BK * LDW * 2)/* 29184 B */
#define STAGE_BYTES (2 * BM * LDA * 2 + 2 * BK * LDW * 2)  /* 37888 B */
#define GEMM_SMEM (2 * STAGE_BYTES)             /* 75776 B */

__device__ __forceinline__ void gemm_load_stage(unsigned char* smem, uint32_t smem_u32,
                                                int stage, int kc, int m0, int n0, int tid) {
    const unsigned char* base = smem + stage * STAGE_BYTES; (void)base;
    uint32_t sb = smem_u32 + stage * STAGE_BYTES;
    // A hi/lo: 128 rows x 32 cols -> 512 uint4 per array, 2 per thread
    #pragma unroll
    for (int it = 0; it < 2; it++) {
        int i = tid + it * 256;
        int row = i >> 2, c8 = (i & 3) * 8;
        size_t src = (size_t)(m0 + row) * 256 + kc * BK + c8;
        uint32_t dst = (uint32_t)(row * LDA + c8) * 2;
        CP_ASYNC16(sb + STG_AH + dst, g_Ah + src);
        CP_ASYNC16(sb + STG_AL + dst, g_Al + src);
    }
    // W hi/lo: 32 rows x 128 cols -> 512 uint4 per array, 2 per thread
    #pragma unroll
    for (int it = 0; it < 2; it++) {
        int i = tid + it * 256;
        int row = i >> 4, c8 = (i & 15) * 8;
        size_t src = (size_t)(kc * BK + row) * 512 + n0 + c8;
        uint32_t dst = (uint32_t)(row * LDW + c8) * 2;
        CP_ASYNC16(sb + STG_WH + dst, g_Wh + src);
        CP_ASYNC16(sb + STG_WL + dst, g_Wl + src);
    }
}

__global__ __launch_bounds__(256) void gemm_wmma_kernel() {
    extern __shared__ __align__(16) unsigned char smem[];
    uint32_t smem_u32 = (uint32_t)__cvta_generic_to_shared(smem);

    const int tid = threadIdx.x;
    const int wid = tid >> 5;
    const int warp_m = wid & 3;        // 0..3 -> 32-row slice
    const int warp_n = wid >> 2;       // 0..1 -> 64-col slice
    const int n0 = blockIdx.x * BN;    // n fastest: CTAs sharing A run adjacently
    const int m0 = blockIdx.y * BM;

    wmma::fragment<wmma::accumulator, 16, 16, 16, float> c[2][4];
    #pragma unroll
    for (int i = 0; i < 2; i++)
        #pragma unroll
        for (int j = 0; j < 4; j++) wmma::fill_fragment(c[i][j], 0.0f);

    gemm_load_stage(smem, smem_u32, 0, 0, m0, n0, tid);
    CP_COMMIT();

    #pragma unroll 1
    for (int kc = 0; kc < 8; kc++) {
        if (kc < 7) {
            gemm_load_stage(smem, smem_u32, (kc + 1) & 1, kc + 1, m0, n0, tid);
            CP_COMMIT();
            CP_WAIT(1);
        } else {
            CP_WAIT(0);
        }
        __syncthreads();

        const unsigned char* st = smem + (kc & 1) * STAGE_BYTES;
        const __nv_bfloat16* sAh = reinterpret_cast<const __nv_bfloat16*>(st + STG_AH);
        const __nv_bfloat16* sAl = reinterpret_cast<const __nv_bfloat16*>(st + STG_AL);
        const __nv_bfloat16* sWh = reinterpret_cast<const __nv_bfloat16*>(st + STG_WH);
        const __nv_bfloat16* sWl = reinterpret_cast<const __nv_bfloat16*>(st + STG_WL);

        #pragma unroll
        for (int ks = 0; ks < BK; ks += 16) {
            wmma::fragment<wmma::matrix_a, 16, 16, 16, __nv_bfloat16, wmma::row_major> ah[2], al[2];
            wmma::fragment<wmma::matrix_b, 16, 16, 16, __nv_bfloat16, wmma::row_major> bh[4], bl[4];
            #pragma unroll
            for (int i = 0; i < 2; i++) {
                const __nv_bfloat16* ap = sAh + (size_t)(warp_m * 32 + i * 16) * LDA + ks;
                const __nv_bfloat16* lp = sAl + (size_t)(warp_m * 32 + i * 16) * LDA + ks;
                wmma::load_matrix_sync(ah[i], ap, LDA);
                wmma::load_matrix_sync(al[i], lp, LDA);
            }
            #pragma unroll
            for (int j = 0; j < 4; j++) {
                const __nv_bfloat16* bp = sWh + (size_t)ks * LDW + warp_n * 64 + j * 16;
                const __nv_bfloat16* lp = sWl + (size_t)ks * LDW + warp_n * 64 + j * 16;
                wmma::load_matrix_sync(bh[j], bp, LDW);
                wmma::load_matrix_sync(bl[j], lp, LDW);
            }
            #pragma unroll
            for (int i = 0; i < 2; i++)
                #pragma unroll
                for (int j = 0; j < 4; j++) {
                    wmma::mma_sync(c[i][j], ah[i], bh[j], c[i][j]);
                    wmma::mma_sync(c[i][j], ah[i], bl[j], c[i][j]);
                    wmma::mma_sync(c[i][j], al[i], bh[j], c[i][j]);
                }
        }
        __syncthreads();
    }

    #pragma unroll
    for (int i = 0; i < 2; i++)
        #pragma unroll
        for (int j = 0; j < 4; j++) {
            float* dst = g_PQ + (size_t)(m0 + warp_m * 32 + i * 16) * 512
                              + n0 + warp_n * 64 + j * 16;
            wmma::store_matrix_sync(dst, c[i][j], 512, wmma::mem_row_major);
        }
}

// ---------------- per-edge logits + segment max ----------------
__global__ __launch_bounds__(256) void edge_kernel(const unsigned* __restrict__ lm,
                                                   const unsigned* __restrict__ batchw,
                                                   const float* __restrict__ b1,
                                                   const float* __restrict__ W2,
                                                   const float* __restrict__ b2) {
    __shared__ float sb1[HIDDEN];
    __shared__ float sW2[HIDDEN];
    __shared__ float sb2;
    const int tid = threadIdx.x;
    if (tid < HIDDEN) { sb1[tid] = b1[tid]; sW2[tid] = W2[tid]; }
    if (tid == 0) sb2 = b2[0];
    __syncthreads();

    const int warp = tid >> 5;
    const int lane = tid & 31;
    const int e = blockIdx.x * 8 + warp;
    if (e >= N_MOVES) return;

    const int is64 = g_is64;
    unsigned s, t;
    if (is64) {
        s = lm[2 * (size_t)e];
        t = lm[2 * ((size_t)N_MOVES + e)];
    } else {
        s = lm[e];
        t = lm[(size_t)N_MOVES + e];
    }

    const float4* P = reinterpret_cast<const float4*>(g_PQ + (size_t)s * 512);
    const float4* Q = reinterpret_cast<const float4*>(g_PQ + (size_t)t * 512 + 256);

    float acc = 0.0f;
    #pragma unroll
    for (int it = 0; it < 2; it++) {
        int j4 = lane + it * 32;
        float4 p = P[j4];
        float4 q = Q[j4];
        int j = j4 * 4;
        float h;
        h = p.x + q.x + sb1[j + 0]; h = fmaxf(h, 0.f); acc = fmaf(h, sW2[j + 0], acc);
        h = p.y + q.y + sb1[j + 1]; h = fmaxf(h, 0.f); acc = fmaf(h, sW2[j + 1], acc);
        h = p.z + q.z + sb1[j + 2]; h = fmaxf(h, 0.f); acc = fmaf(h, sW2[j + 2], acc);
        h = p.w + q.w + sb1[j + 3]; h = fmaxf(h, 0.f); acc = fmaf(h, sW2[j + 3], acc);
    }
    #pragma unroll
    for (int o = 16; o > 0; o >>= 1)
        acc += __shfl_down_sync(0xffffffffu, acc, o);

    if (lane == 0) {
        float logit = acc + sb2;
        unsigned g = is64 ? batchw[2 * (size_t)s] : batchw[s];
        g_logits[e] = logit;
        g_mb[e] = (int)g;
        atomicMax(&g_gmax[g], enc_f(logit));
    }
}

// ---------------- exp + segment sum ----------------
__global__ void expsum_kernel(float* __restrict__ out) {
    int e = blockIdx.x * blockDim.x + threadIdx.x;
    if (e >= N_MOVES) return;
    int g = g_mb[e];
    float m = dec_f(g_gmax[g]);
    float ex = expf(g_logits[e] - m);
    out[e] = ex;
    atomicAdd(&g_gsum[g], ex);
}

// ---------------- normalize ----------------
__global__ void norm_kernel(float* __restrict__ out) {
    int e = blockIdx.x * blockDim.x + threadIdx.x;
    if (e >= N_MOVES) return;
    out[e] = out[e] / (g_gsum[g_mb[e]] + 1e-16f);
}

// ---------------- launch ----------------
extern "C" void kernel_launch(void* const* d_in, const int* in_sizes, int n_in,
                              void* d_out, int out_size) {
    const float*    emb    = (const float*)d_in[0];
    const unsigned* lm     = (const unsigned*)d_in[1];
    const unsigned* batchw = (const unsigned*)d_in[2];
    const float*    W1     = (const float*)d_in[3];
    const float*    b1     = (const float*)d_in[4];
    const float*    W2     = (const float*)d_in[5];
    const float*    b2     = (const float*)d_in[6];
    float*          out    = (float*)d_out;
    (void)in_sizes; (void)n_in; (void)out_size;

    cudaFuncSetAttribute(gemm_wmma_kernel, cudaFuncAttributeMaxDynamicSharedMemorySize, GEMM_SMEM);

    detect_kernel<<<1, 32>>>(lm);
    init_kernel<<<1, N_GRAPHS>>>();

    aconv_kernel<<<(M_PAD * 32 + 255) / 256, 256>>>(emb);
    wprep_kernel<<<(2 * 256 * 256 + 255) / 256, 256>>>(W1);

    dim3 ggrid(512 / BN, M_PAD / BM);   // x = n tile (fast), y = m tile
    gemm_wmma_kernel<<<ggrid, 256, GEMM_SMEM>>>();

    edge_kernel<<<N_MOVES / 8, 256>>>(lm, batchw, b1, W2, b2);

    int eb = (N_MOVES + 255) / 256;
    expsum_kernel<<<eb, 256>>>(out);
    norm_kernel<<<eb, 256>>>(out);
}

// round 8
// speedup vs baseline: 2.2896x; 1.6512x over previous
#include <cuda_runtime.h>
#include <cuda_fp16.h>
#include <mma.h>
#include <cstdint>

using namespace nvcuda;

#define N_NODES  100000
#define HIDDEN   256
#define N_MOVES  500000
#define N_GRAPHS 512
#define M_PAD    100096            /* divisible by 128 (782 * 128) */

// ---------------- scratch (static __device__ — no allocations) ----------------
__device__ __half  g_Ah[(size_t)M_PAD * 256];
__device__ __half  g_Wh[256 * 512];
__device__ float    g_PQ[(size_t)M_PAD * 512];   // [n][0:256]=P, [n][256:512]=Q
__device__ float    g_logits[N_MOVES];
__device__ int      g_mb[N_MOVES];
__device__ unsigned g_gmax[N_GRAPHS];
__device__ float    g_gsum[N_GRAPHS];
__device__ int      g_is64;

__device__ __forceinline__ unsigned enc_f(float f) {
    unsigned u = __float_as_uint(f);
    return (u & 0x80000000u) ? ~u : (u | 0x80000000u);
}
__device__ __forceinline__ float dec_f(unsigned u) {
    u = (u & 0x80000000u) ? (u & 0x7fffffffu) : ~u;
    return __uint_as_float(u);
}

// ---------------- cp.async helpers ----------------
#define CP_ASYNC16(dst_u32, src_ptr) \
    asm volatile("cp.async.cg.shared.global [%0], [%1], 16;" :: "r"(dst_u32), "l"(src_ptr))
#define CP_COMMIT() asm volatile("cp.async.commit_group;")
#define CP_WAIT(n)  asm volatile("cp.async.wait_group %0;" :: "n"(n))

// ---------------- dtype detection: int64 vs int32 index arrays ----------------
__global__ void detect_kernel(const unsigned* __restrict__ lm) {
    if (threadIdx.x == 0 && blockIdx.x == 0) {
        int all0 = 1;
        #pragma unroll 1
        for (int i = 1; i < 128; i += 2) all0 &= (lm[i] == 0u);
        g_is64 = all0;
    }
}

__global__ void init_kernel() {
    int i = blockIdx.x * blockDim.x + threadIdx.x;
    if (i < N_GRAPHS) { g_gmax[i] = 0u; g_gsum[i] = 0.0f; }
}

// ---------------- A conversion: fp32 -> fp16 (linear layout) ----------------
__global__ __launch_bounds__(256) void aconv_kernel(const float* __restrict__ emb) {
    int idx = blockIdx.x * blockDim.x + threadIdx.x;   // one thread = 8 k of one row
    if (idx >= M_PAD * 32) return;
    int r  = idx >> 5;
    int k0 = (idx & 31) * 8;
    float v[8];
    if (r < N_NODES) {
        const float4* p = reinterpret_cast<const float4*>(emb + (size_t)r * HIDDEN + k0);
        float4 x = p[0], y = p[1];
        v[0] = x.x; v[1] = x.y; v[2] = x.z; v[3] = x.w;
        v[4] = y.x; v[5] = y.y; v[6] = y.z; v[7] = y.w;
    } else {
        #pragma unroll
        for (int i = 0; i < 8; i++) v[i] = 0.0f;
    }
    __align__(16) __half h[8];
    #pragma unroll
    for (int i = 0; i < 8; i++) h[i] = __float2half(v[i]);
    *reinterpret_cast<uint4*>(g_Ah + (size_t)r * 256 + k0) = *reinterpret_cast<uint4*>(h);
}

// ---------------- W prep: W1 (512,256) -> combined [256 k][512 n] fp16 ------
// n < 256: W[k][n] = W1[k][n];  n >= 256: W[k][n] = W1[256+k][n-256]
__global__ __launch_bounds__(256) void wprep_kernel(const float* __restrict__ W1) {
    int idx = blockIdx.x * blockDim.x + threadIdx.x;   // 0..131071
    if (idx >= 2 * 256 * 256) return;
    int n = idx & 255;
    int k = (idx >> 8) & 255;
    int T = idx >> 16;
    float v = W1[((size_t)(T * 256 + k)) * 256 + n];
    g_Wh[(size_t)k * 512 + T * 256 + n] = __float2half(v);
}

// ---------------- WMMA fp16 GEMM, cp.async double-buffered ----------------
// CTA tile 128x128, 8 warps (4m x 2n), warp tile 32x64, BK=32, 2 stages.
#define BM 128
#define BN 128
#define BK 32
#define LDA 40     /* 32 + 8 pad; row = 80B (16B mult) */
#define LDW 136    /* 128 + 8 pad; row = 272B (16B mult) */
#define STG_A 0
#define STG_W (BM * LDA * 2)                     /* 10240 B */
#define STAGE_BYTES (BM * LDA * 2 + BK * LDW * 2)   /* 18944 B */
#define GEMM_SMEM (2 * STAGE_BYTES)              /* 37888 B */

__device__ __forceinline__ void gemm_load_stage(uint32_t smem_u32,
                                                int stage, int kc, int m0, int n0, int tid) {
    uint32_t sb = smem_u32 + stage * STAGE_BYTES;
    // A: 128 rows x 32 cols -> 512 uint4, 2 per thread
    #pragma unroll
    for (int it = 0; it < 2; it++) {
        int i = tid + it * 256;
        int row = i >> 2, c8 = (i & 3) * 8;
        size_t src = (size_t)(m0 + row) * 256 + kc * BK + c8;
        uint32_t dst = (uint32_t)(row * LDA + c8) * 2;
        CP_ASYNC16(sb + STG_A + dst, g_Ah + src);
    }
    // W: 32 rows x 128 cols -> 512 uint4, 2 per thread
    #pragma unroll
    for (int it = 0; it < 2; it++) {
        int i = tid + it * 256;
        int row = i >> 4, c8 = (i & 15) * 8;
        size_t src = (size_t)(kc * BK + row) * 512 + n0 + c8;
        uint32_t dst = (uint32_t)(row * LDW + c8) * 2;
        CP_ASYNC16(sb + STG_W + dst, g_Wh + src);
    }
}

__global__ __launch_bounds__(256) void gemm_wmma_kernel() {
    extern __shared__ __align__(16) unsigned char smem[];
    uint32_t smem_u32 = (uint32_t)__cvta_generic_to_shared(smem);

    const int tid = threadIdx.x;
    const int wid = tid >> 5;
    const int warp_m = wid & 3;        // 0..3 -> 32-row slice
    const int warp_n = wid >> 2;       // 0..1 -> 64-col slice
    const int n0 = blockIdx.x * BN;    // n fastest: CTAs sharing A run adjacently
    const int m0 = blockIdx.y * BM;

    wmma::fragment<wmma::accumulator, 16, 16, 16, float> c[2][4];
    #pragma unroll
    for (int i = 0; i < 2; i++)
        #pragma unroll
        for (int j = 0; j < 4; j++) wmma::fill_fragment(c[i][j], 0.0f);

    gemm_load_stage(smem_u32, 0, 0, m0, n0, tid);
    CP_COMMIT();

    #pragma unroll 1
    for (int kc = 0; kc < 8; kc++) {
        if (kc < 7) {
            gemm_load_stage(smem_u32, (kc + 1) & 1, kc + 1, m0, n0, tid);
            CP_COMMIT();
            CP_WAIT(1);
        } else {
            CP_WAIT(0);
        }
        __syncthreads();

        const unsigned char* st = smem + (kc & 1) * STAGE_BYTES;
        const __half* sA = reinterpret_cast<const __half*>(st + STG_A);
        const __half* sW = reinterpret_cast<const __half*>(st + STG_W);

        #pragma unroll
        for (int ks = 0; ks < BK; ks += 16) {
            wmma::fragment<wmma::matrix_a, 16, 16, 16, __half, wmma::row_major> a[2];
            wmma::fragment<wmma::matrix_b, 16, 16, 16, __half, wmma::row_major> b[4];
            #pragma unroll
            for (int i = 0; i < 2; i++)
                wmma::load_matrix_sync(a[i], sA + (size_t)(warp_m * 32 + i * 16) * LDA + ks, LDA);
            #pragma unroll
            for (int j = 0; j < 4; j++)
                wmma::load_matrix_sync(b[j], sW + (size_t)ks * LDW + warp_n * 64 + j * 16, LDW);
            #pragma unroll
            for (int i = 0; i < 2; i++)
                #pragma unroll
                for (int j = 0; j < 4; j++)
                    wmma::mma_sync(c[i][j], a[i], b[j], c[i][j]);
        }
        __syncthreads();
    }

    #pragma unroll
    for (int i = 0; i < 2; i++)
        #pragma unroll
        for (int j = 0; j < 4; j++) {
            float* dst = g_PQ + (size_t)(m0 + warp_m * 32 + i * 16) * 512
                              + n0 + warp_n * 64 + j * 16;
            wmma::store_matrix_sync(dst, c[i][j], 512, wmma::mem_row_major);
        }
}

// ---------------- per-edge logits + segment max ----------------
__global__ __launch_bounds__(256) void edge_kernel(const unsigned* __restrict__ lm,
                                                   const unsigned* __restrict__ batchw,
                                                   const float* __restrict__ b1,
                                                   const float* __restrict__ W2,
                                                   const float* __restrict__ b2) {
    __shared__ float sb1[HIDDEN];
    __shared__ float sW2[HIDDEN];
    __shared__ float sb2;
    const int tid = threadIdx.x;
    if (tid < HIDDEN) { sb1[tid] = b1[tid]; sW2[tid] = W2[tid]; }
    if (tid == 0) sb2 = b2[0];
    __syncthreads();

    const int warp = tid >> 5;
    const int lane = tid & 31;
    const int e = blockIdx.x * 8 + warp;
    if (e >= N_MOVES) return;

    const int is64 = g_is64;
    unsigned s, t;
    if (is64) {
        s = lm[2 * (size_t)e];
        t = lm[2 * ((size_t)N_MOVES + e)];
    } else {
        s = lm[e];
        t = lm[(size_t)N_MOVES + e];
    }

    const float4* P = reinterpret_cast<const float4*>(g_PQ + (size_t)s * 512);
    const float4* Q = reinterpret_cast<const float4*>(g_PQ + (size_t)t * 512 + 256);

    float acc = 0.0f;
    #pragma unroll
    for (int it = 0; it < 2; it++) {
        int j4 = lane + it * 32;
        float4 p = P[j4];
        float4 q = Q[j4];
        int j = j4 * 4;
        float h;
        h = p.x + q.x + sb1[j + 0]; h = fmaxf(h, 0.f); acc = fmaf(h, sW2[j + 0], acc);
        h = p.y + q.y + sb1[j + 1]; h = fmaxf(h, 0.f); acc = fmaf(h, sW2[j + 1], acc);
        h = p.z + q.z + sb1[j + 2]; h = fmaxf(h, 0.f); acc = fmaf(h, sW2[j + 2], acc);
        h = p.w + q.w + sb1[j + 3]; h = fmaxf(h, 0.f); acc = fmaf(h, sW2[j + 3], acc);
    }
    #pragma unroll
    for (int o = 16; o > 0; o >>= 1)
        acc += __shfl_down_sync(0xffffffffu, acc, o);

    if (lane == 0) {
        float logit = acc + sb2;
        unsigned g = is64 ? batchw[2 * (size_t)s] : batchw[s];
        g_logits[e] = logit;
        g_mb[e] = (int)g;
        atomicMax(&g_gmax[g], enc_f(logit));
    }
}

// ---------------- exp + segment sum ----------------
__global__ void expsum_kernel(float* __restrict__ out) {
    int e = blockIdx.x * blockDim.x + threadIdx.x;
    if (e >= N_MOVES) return;
    int g = g_mb[e];
    float m = dec_f(g_gmax[g]);
    float ex = expf(g_logits[e] - m);
    out[e] = ex;
    atomicAdd(&g_gsum[g], ex);
}

// ---------------- normalize ----------------
__global__ void norm_kernel(float* __restrict__ out) {
    int e = blockIdx.x * blockDim.x + threadIdx.x;
    if (e >= N_MOVES) return;
    out[e] = out[e] / (g_gsum[g_mb[e]] + 1e-16f);
}

// ---------------- launch ----------------
extern "C" void kernel_launch(void* const* d_in, const int* in_sizes, int n_in,
                              void* d_out, int out_size) {
    const float*    emb    = (const float*)d_in[0];
    const unsigned* lm     = (const unsigned*)d_in[1];
    const unsigned* batchw = (const unsigned*)d_in[2];
    const float*    W1     = (const float*)d_in[3];
    const float*    b1     = (const float*)d_in[4];
    const float*    W2     = (const float*)d_in[5];
    const float*    b2     = (const float*)d_in[6];
    float*          out    = (float*)d_out;
    (void)in_sizes; (void)n_in; (void)out_size;

    cudaFuncSetAttribute(gemm_wmma_kernel, cudaFuncAttributeMaxDynamicSharedMemorySize, GEMM_SMEM);

    detect_kernel<<<1, 32>>>(lm);
    init_kernel<<<1, N_GRAPHS>>>();

    aconv_kernel<<<(M_PAD * 32 + 255) / 256, 256>>>(emb);
    wprep_kernel<<<(2 * 256 * 256 + 255) / 256, 256>>>(W1);

    dim3 ggrid(512 / BN, M_PAD / BM);   // x = n tile (fast), y = m tile
    gemm_wmma_kernel<<<ggrid, 256, GEMM_SMEM>>>();

    edge_kernel<<<N_MOVES / 8, 256>>>(lm, batchw, b1, W2, b2);

    int eb = (N_MOVES + 255) / 256;
    expsum_kernel<<<eb, 256>>>(out);
    norm_kernel<<<eb, 256>>>(out);
}